// round 6
// baseline (speedup 1.0000x reference)
#include <cuda_runtime.h>
#include <cuda_bf16.h>

#define NF   100000
#define CLIP 50
#define D    64
#define NT   7    // iterations: 8 friends each (56 slots, 6 padded)
#define PF   2    // pipeline depth

// 4 lanes per friend, 8 friends per warp-iteration, 7 iterations.
// logits = sum_c gate_c * pd_c / nfr  (pd_c = dot(fe_c, ie*w) = pre-sigmoid value)
__global__ __launch_bounds__(256, 3)
void gmf_kernel(const int*   __restrict__ user_indices,
                const int*   __restrict__ item_indices,
                const int*   __restrict__ ufi,          // [100000, 50]
                const float* __restrict__ emb_user,     // [100001, 64] (row NF == 0)
                const float* __restrict__ emb_item,     // [100000, 64]
                const float* __restrict__ affine_w,     // [64]
                const float* __restrict__ affine_b,     // scalar
                float*       __restrict__ rating_out,   // [B]
                float*       __restrict__ gidx_out,     // [B, 50] or null
                int B)
{
    const int warp = (int)((blockIdx.x * blockDim.x + threadIdx.x) >> 5);
    const int lane = threadIdx.x & 31;
    if (warp >= B) return;

    const int lgi = lane & 3;    // lane in 4-lane group
    const int grp = lane >> 2;   // friend-group 0..7

    const int   u    = user_indices[warp];
    const int   it   = item_indices[warp];
    const float bias = *affine_b;

    // lane holds float4 indices {lgi, 4+lgi, 8+lgi, 12+lgi} of (item_emb * w)
    float4 iw[4];
    {
        const float4* ie = (const float4*)(emb_item + (size_t)it * D);
        const float4* w  = (const float4*)affine_w;
        #pragma unroll
        for (int k = 0; k < 4; ++k) {
            float4 a = ie[4 * k + lgi];
            float4 b = w [4 * k + lgi];
            iw[k] = make_float4(a.x*b.x, a.y*b.y, a.z*b.z, a.w*b.w);
        }
    }

    const int* friends = ufi + (size_t)u * CLIP;

    // preload friend ids (uniform within 4-lane group; L1/L2 resident)
    int fid[NT];
    #pragma unroll
    for (int t = 0; t < NT; ++t) {
        const int c = 8 * t + grp;               // slot 0..55
        fid[t] = (c < CLIP) ? friends[c] : NF;
    }

    float4 buf[PF][4];                           // pipeline buffers

    #pragma unroll
    for (int p = 0; p < PF; ++p) {
        const float4* fr = (const float4*)(emb_user + (size_t)fid[p] * D);
        #pragma unroll
        for (int k = 0; k < 4; ++k) buf[p][k] = fr[4 * k + lgi];
    }

    float s   = 0.f;             // sum gate*pd (uniform within group)
    int   nfr = 0;               // friend count (uniform within group)
    float ga = 0.f, gb = 0.f;    // gate stash: t==lgi, t==lgi+4

    #pragma unroll
    for (int t = 0; t < NT; ++t) {
        const int slot = t % PF;
        float4 b0 = buf[slot][0], b1 = buf[slot][1];
        float4 b2 = buf[slot][2], b3 = buf[slot][3];

        if (t + PF < NT) {
            const float4* fr = (const float4*)(emb_user + (size_t)fid[t + PF] * D);
            #pragma unroll
            for (int k = 0; k < 4; ++k) buf[slot][k] = fr[4 * k + lgi];
        }

        float pd = b0.x*iw[0].x + b0.y*iw[0].y + b0.z*iw[0].z + b0.w*iw[0].w
                 + b1.x*iw[1].x + b1.y*iw[1].y + b1.z*iw[1].z + b1.w*iw[1].w
                 + b2.x*iw[2].x + b2.y*iw[2].y + b2.z*iw[2].z + b2.w*iw[2].w
                 + b3.x*iw[3].x + b3.y*iw[3].y + b3.z*iw[3].z + b3.w*iw[3].w;
        pd += __shfl_xor_sync(0xffffffffu, pd, 2);
        pd += __shfl_xor_sync(0xffffffffu, pd, 1);

        const float gate = 1.f / (1.f + __expf(-(pd + bias)));

        s   += gate * pd;            // padded slots: pd==0 -> contributes 0
        nfr += (fid[t] != NF);

        if (t == lgi)     ga = gate;   // covers t=0..3
        if (t == lgi + 4) gb = gate;   // covers t=4..6
    }

    // ---- gate output: slot(t,grp) = 8*t + grp ----
    if (gidx_out) {
        float* gp = gidx_out + (size_t)warp * CLIP;
        gp[8 * lgi + grp] = ga;                          // slots 0..31
        const int c2 = 32 + 8 * lgi + grp;               // slots 32..55
        if (c2 < CLIP) gp[c2] = gb;
    }

    // ---- combine the 8 groups (values uniform within each 4-lane group) ----
    s   += __shfl_xor_sync(0xffffffffu, s, 4);
    s   += __shfl_xor_sync(0xffffffffu, s, 8);
    s   += __shfl_xor_sync(0xffffffffu, s, 16);
    nfr += __shfl_xor_sync(0xffffffffu, nfr, 4);
    nfr += __shfl_xor_sync(0xffffffffu, nfr, 8);
    nfr += __shfl_xor_sync(0xffffffffu, nfr, 16);

    if (lane == 0) {
        const float logit = s / (float)nfr + bias;   // nfr==0 -> inf/nan, matches ref
        rating_out[warp] = 1.f / (1.f + __expf(-logit));
    }
}

extern "C" void kernel_launch(void* const* d_in, const int* in_sizes, int n_in,
                              void* d_out, int out_size)
{
    const int*   user_indices = (const int*)  d_in[0];
    const int*   item_indices = (const int*)  d_in[1];
    const int*   ufi          = (const int*)  d_in[2];
    const float* emb_user     = (const float*)d_in[3];
    const float* emb_item     = (const float*)d_in[4];
    const float* affine_w     = (const float*)d_in[5];
    const float* affine_b     = (const float*)d_in[6];

    const int B = in_sizes[0];
    float* out = (float*)d_out;

    float* rating = out;
    float* gidx   = (out_size >= B * (1 + CLIP)) ? (out + B) : nullptr;

    const int threads = 256;                 // 8 warps/block, 1 warp per batch row
    const int blocks  = (B * 32 + threads - 1) / threads;
    gmf_kernel<<<blocks, threads>>>(user_indices, item_indices, ufi,
                                    emb_user, emb_item, affine_w, affine_b,
                                    rating, gidx, B);
}

// round 7
// speedup vs baseline: 1.1892x; 1.1892x over previous
#include <cuda_runtime.h>
#include <cuda_bf16.h>
#include <cstdint>

#define NF   100000
#define CLIP 50
#define D    64
#define NT   13   // friend-slot iterations (4 friends each; 52 slots, 2 padded)
#define PF   4    // software-pipeline depth

// float4 gather with L2 evict_last policy (keeps emb_user table L2-resident)
__device__ __forceinline__ float4 ldg_pol(const float4* p, uint64_t pol) {
    float4 v;
    asm volatile("ld.global.L2::cache_hint.v4.f32 {%0,%1,%2,%3}, [%4], %5;"
                 : "=f"(v.x), "=f"(v.y), "=f"(v.z), "=f"(v.w)
                 : "l"(p), "l"(pol));
    return v;
}

// 8 lanes per friend, 4 friends per warp-iteration, 13 iterations.
// logits = sum_c gate_c * pd_c / nfr  (pd_c = dot(fe_c, ie*w) is the pre-sigmoid value)
__global__ __launch_bounds__(256, 3)
void gmf_kernel(const int*   __restrict__ user_indices,
                const int*   __restrict__ item_indices,
                const int*   __restrict__ ufi,          // [100000, 50]
                const float* __restrict__ emb_user,     // [100001, 64] (row NF == 0)
                const float* __restrict__ emb_item,     // [100000, 64]
                const float* __restrict__ affine_w,     // [64]
                const float* __restrict__ affine_b,     // scalar
                float*       __restrict__ rating_out,   // [B]
                float*       __restrict__ gidx_out,     // [B, 50] or null
                int B)
{
    const int warp = (int)((blockIdx.x * blockDim.x + threadIdx.x) >> 5);
    const int lane = threadIdx.x & 31;
    if (warp >= B) return;

    const int lig = lane & 7;    // lane in 8-lane group
    const int grp = lane >> 3;   // friend-group 0..3

    uint64_t pol;
    asm volatile("createpolicy.fractional.L2::evict_last.b64 %0, 1.0;" : "=l"(pol));

    const int   u    = user_indices[warp];
    const int   it   = item_indices[warp];
    const float bias = *affine_b;

    // lane holds dims [4*lig, 4*lig+4) and [32+4*lig, ...) of item*w
    float4 iw_lo, iw_hi;
    {
        const float4* ie = (const float4*)(emb_item + (size_t)it * D);
        const float4* w  = (const float4*)affine_w;
        float4 a = ie[lig],     b0 = w[lig];
        float4 c = ie[lig + 8], d0 = w[lig + 8];
        iw_lo = make_float4(a.x*b0.x, a.y*b0.y, a.z*b0.z, a.w*b0.w);
        iw_hi = make_float4(c.x*d0.x, c.y*d0.y, c.z*d0.z, c.w*d0.w);
    }

    const int* friends = ufi + (size_t)u * CLIP;

    // preload friend ids (uniform per 8-lane group; L1/L2 resident)
    int fid[NT];
    #pragma unroll
    for (int t = 0; t < NT; ++t) {
        const int c = 4 * t + grp;
        fid[t] = (c < CLIP) ? friends[c] : NF;
    }

    float4 blo[PF], bhi[PF];     // pipeline buffers (compile-time indexed)

    // ---- prologue: issue loads for t = 0..PF-1
    #pragma unroll
    for (int t = 0; t < PF; ++t) {
        const float4* fr = (const float4*)(emb_user + (size_t)fid[t] * D);
        blo[t] = ldg_pol(fr + lig,     pol);
        bhi[t] = ldg_pol(fr + lig + 8, pol);
    }

    float s   = 0.f;             // sum of gate*pd (uniform within 8-lane group)
    int   nfr = 0;
    float ga = 0.f, gb = 0.f;    // gate stash: t==lig, t==lig+8

    // ---- steady state: prefetch t+PF, compute t
    #pragma unroll
    for (int t = 0; t < NT; ++t) {
        const int slot = t % PF;
        const float4 f_lo = blo[slot];
        const float4 f_hi = bhi[slot];

        if (t + PF < NT) {
            const float4* fr = (const float4*)(emb_user + (size_t)fid[t + PF] * D);
            blo[slot] = ldg_pol(fr + lig,     pol);
            bhi[slot] = ldg_pol(fr + lig + 8, pol);
        }

        float pd = f_lo.x*iw_lo.x + f_lo.y*iw_lo.y + f_lo.z*iw_lo.z + f_lo.w*iw_lo.w
                 + f_hi.x*iw_hi.x + f_hi.y*iw_hi.y + f_hi.z*iw_hi.z + f_hi.w*iw_hi.w;
        pd += __shfl_xor_sync(0xffffffffu, pd, 4);
        pd += __shfl_xor_sync(0xffffffffu, pd, 2);
        pd += __shfl_xor_sync(0xffffffffu, pd, 1);

        const float gate = 1.f / (1.f + __expf(-(pd + bias)));

        s   += gate * pd;            // padded slots: pd==0 -> contributes 0
        nfr += (fid[t] != NF);

        if (t == lig)     ga = gate;   // covers t=0..7
        if (t == lig + 8) gb = gate;   // covers t=8..12
    }

    // ---- gate output: gp[4*t + grp], coalesced across the warp ----
    if (gidx_out) {
        float* gp = gidx_out + (size_t)warp * CLIP;
        gp[4 * lig + grp] = ga;                          // slots 0..31
        const int c2 = 32 + 4 * lig + grp;               // slots 32..49 (+2 padded)
        if (c2 < CLIP) gp[c2] = gb;
    }

    // ---- combine the 4 groups (values uniform within each group) ----
    s   += __shfl_xor_sync(0xffffffffu, s, 8);
    s   += __shfl_xor_sync(0xffffffffu, s, 16);
    nfr += __shfl_xor_sync(0xffffffffu, nfr, 8);
    nfr += __shfl_xor_sync(0xffffffffu, nfr, 16);

    if (lane == 0) {
        const float logit = s / (float)nfr + bias;   // nfr==0 -> inf/nan, matches ref
        rating_out[warp] = 1.f / (1.f + __expf(-logit));
    }
}

extern "C" void kernel_launch(void* const* d_in, const int* in_sizes, int n_in,
                              void* d_out, int out_size)
{
    const int*   user_indices = (const int*)  d_in[0];
    const int*   item_indices = (const int*)  d_in[1];
    const int*   ufi          = (const int*)  d_in[2];
    const float* emb_user     = (const float*)d_in[3];
    const float* emb_item     = (const float*)d_in[4];
    const float* affine_w     = (const float*)d_in[5];
    const float* affine_b     = (const float*)d_in[6];

    const int B = in_sizes[0];
    float* out = (float*)d_out;

    float* rating = out;
    float* gidx   = (out_size >= B * (1 + CLIP)) ? (out + B) : nullptr;

    const int threads = 256;                 // 8 warps/block, 1 warp per batch row
    const int blocks  = (B * 32 + threads - 1) / threads;
    gmf_kernel<<<blocks, threads>>>(user_indices, item_indices, ufi,
                                    emb_user, emb_item, affine_w, affine_b,
                                    rating, gidx, B);
}